// round 16
// baseline (speedup 1.0000x reference)
#include <cuda_runtime.h>
#include <math.h>

#define NN 8
#define HH 12
#define DHD 64
#define LV 1568
#define LA 512
#define NCV 392
#define NCA 256
#define NHNH (NN*HH)          // 96
#define OSTR 5696             // output row stride
#define RS_V 8
#define RS_A 8
#define SCALEF 0.125f

#define K1_BLOCKS (2 * RS_V * NHNH)   // 1536
#define K2_BLOCKS (RS_A * NHNH)       // 768
#define K3_BLOCKS (2 * NHNH)          // 192
#define SUM_BLOCKS NN                 // 8
#define FILL_BLOCKS (4 * NN)          // 32
#define CHUNK 8
#define CH_V (NCV / CHUNK)            // 49 (exact)
#define CH_A (NCA / CHUNK)            // 32 (exact)

// ---- scratch (device globals; no allocation allowed) ----
// Partials are INTERLEAVED: index = (nh*L + col)*RS + y, so the RS partials of
// one (nh,col) share a single 32B sector for the consumer.
__device__ float g_sum_av[NN];
__device__ float g_sum_va[NN];
__device__ float g_vpos[NHNH * LV * RS_V];
__device__ float g_apos[NHNH * LA * RS_A];

// KBIG: five block families, all depending only on kernel inputs:
//  [0, K1)            : v_pos partials from cross_av (float4 row reads), weights gathered direct
//  [K1, +K2)          : a_pos partials from cross_va (float2 row reads)
//  [+K3)              : cls weighted means (in-block weight gather + sum)
//  [+SUM)             : g_sum_av / g_sum_va for kp
//  [+FILL)            : output defaults (prob=0, prune=n_attn)
__global__ void kbig(const float* __restrict__ cross_av,
                     const float* __restrict__ cross_va,
                     const float* __restrict__ pos_v_q,
                     const float* __restrict__ pos_a_q,
                     const int* __restrict__ ids_a,
                     const int* __restrict__ ids_v,
                     const float* __restrict__ n_attn_av,
                     const float* __restrict__ n_attn_va,
                     float* __restrict__ out) {
    const int bid = blockIdx.x;
    const int t = threadIdx.x;   // 256
    __shared__ __align__(16) char smem_raw[4608];

    if (bid < K1_BLOCKS) {
        int* ridx = (int*)smem_raw;                 // 32
        float* rw = (float*)(smem_raw + 128);       // 32
        const int x = bid & 1;
        const int y = (bid >> 1) & (RS_V - 1);
        const int nh = bid >> 4;
        const int n = nh / HH;
        const int g = x * 256 + t;
        const int RPB = NCA / RS_V;                 // 32

        if (t < RPB) {
            int a = y * RPB + t;
            int id = ids_a[n * LA + a];
            ridx[t] = id;
            rw[t]   = n_attn_va[n * LA + id];
        }
        __syncthreads();
        if (g >= LV / 4) return;

        float4 acc = make_float4(0.f, 0.f, 0.f, 0.f);
        const float4* base = (const float4*)cross_av;
        const size_t nhbase = (size_t)nh * LA * (LV / 4);
#pragma unroll 8
        for (int a = 0; a < RPB; a++) {
            float w = rw[a];
            float4 v = __ldg(base + nhbase + (size_t)ridx[a] * (LV / 4) + g);
            acc.x += w * v.x; acc.y += w * v.y; acc.z += w * v.z; acc.w += w * v.w;
        }
        // interleaved scatter: 4 cols, slot y each (L2-resident buffer)
        float* dst = g_vpos + ((size_t)nh * LV + 4 * g) * RS_V + y;
        dst[0 * RS_V] = acc.x;
        dst[1 * RS_V] = acc.y;
        dst[2 * RS_V] = acc.z;
        dst[3 * RS_V] = acc.w;
    } else if (bid < K1_BLOCKS + K2_BLOCKS) {
        int* ridx = (int*)smem_raw;                 // 49
        float* rw = (float*)(smem_raw + 256);       // 49
        const int b2 = bid - K1_BLOCKS;
        const int y = b2 & (RS_A - 1);
        const int nh = b2 >> 3;
        const int n = nh / HH;
        const int RPB = NCV / RS_A;                 // 49

        if (t < RPB) {
            int v = y * RPB + t;
            int id = ids_v[n * LV + v];
            ridx[t] = id;
            rw[t]   = n_attn_av[n * LV + id];
        }
        __syncthreads();

        float2 acc = make_float2(0.f, 0.f);
        const float2* base = (const float2*)cross_va;
        const size_t nhbase = (size_t)nh * LV * (LA / 2);
#pragma unroll 7
        for (int a = 0; a < RPB; a++) {
            float w = rw[a];
            float2 v = __ldg(base + nhbase + (size_t)ridx[a] * (LA / 2) + t);
            acc.x += w * v.x; acc.y += w * v.y;
        }
        float* dst = g_apos + ((size_t)nh * LA + 2 * t) * RS_A + y;
        dst[0 * RS_A] = acc.x;
        dst[1 * RS_A] = acc.y;
    } else if (bid < K1_BLOCKS + K2_BLOCKS + K3_BLOCKS) {
        // cls: weighted mean over gathered rows of pos_*_q (in-block weight sum)
        int* ridx = (int*)smem_raw;                       // up to 392 ints
        float* rw = (float*)(smem_raw + 1600);            // up to 392 floats
        float* part = (float*)(smem_raw + 3200);          // 4*64 floats
        float* wred = (float*)(smem_raw + 4224);          // 8 warp sums
        const int b3 = bid - (K1_BLOCKS + K2_BLOCKS);
        const int nh = b3 >> 1;
        const bool vside = (b3 & 1) == 0;
        const int n = nh / HH;
        const int h = nh % HH;
        const int d = t & 63;
        const int sub = t >> 6;   // 0..3

        const int cnt = vside ? NCV : NCA;
        const int L = vside ? LV : LA;
        const int* ids = vside ? ids_v : ids_a;
        const float* attn = vside ? n_attn_av : n_attn_va;
        const float* q = vside ? pos_v_q : pos_a_q;

        float lsum = 0.f;
        for (int i = t; i < cnt; i += 256) {
            int id = ids[n * L + i];
            float w = attn[n * L + id];
            ridx[i] = id;
            rw[i]   = w;
            lsum += w;
        }
#pragma unroll
        for (int s = 16; s > 0; s >>= 1) lsum += __shfl_xor_sync(0xffffffff, lsum, s);
        if ((t & 31) == 0) wred[t >> 5] = lsum;
        __syncthreads();

        float acc = 0.f;
        const float* basep = q + (size_t)nh * L * DHD;
#pragma unroll 8
        for (int i = sub; i < cnt; i += 4)
            acc += __ldg(basep + (size_t)ridx[i] * DHD + d) * rw[i];

        part[sub * DHD + d] = acc;
        __syncthreads();

        if (sub == 0) {
            float tot = acc + part[DHD + d] + part[2 * DHD + d] + part[3 * DHD + d];
            float su = 0.f;
#pragma unroll
            for (int w8 = 0; w8 < 8; w8++) su += wred[w8];
            const int off = vside ? 2080 : 2848;
            out[n * OSTR + off + h * DHD + d] = tot / su;
        }
    } else if (bid < K1_BLOCKS + K2_BLOCKS + K3_BLOCKS + SUM_BLOCKS) {
        // sums of gathered weights for kp
        float* red = (float*)smem_raw;   // 256 floats
        const int n = bid - (K1_BLOCKS + K2_BLOCKS + K3_BLOCKS);

        float sv = 0.f;
        for (int i = t; i < NCV; i += 256) {
            int id = ids_v[n * LV + i];
            sv += n_attn_av[n * LV + id];
        }
        red[t] = sv;
        __syncthreads();
        for (int s = 128; s > 0; s >>= 1) {
            if (t < s) red[t] += red[t + s];
            __syncthreads();
        }
        if (t == 0) g_sum_av[n] = red[0];
        __syncthreads();

        float sa = 0.f;
        for (int i = t; i < NCA; i += 256) {
            int id = ids_a[n * LA + i];
            sa += n_attn_va[n * LA + id];
        }
        red[t] = sa;
        __syncthreads();
        for (int s = 128; s > 0; s >>= 1) {
            if (t < s) red[t] += red[t + s];
            __syncthreads();
        }
        if (t == 0) g_sum_va[n] = red[0];
    } else {
        // output defaults
        const int b5 = bid - (K1_BLOCKS + K2_BLOCKS + K3_BLOCKS + SUM_BLOCKS);
        const int n = b5 >> 2;
        const int p = b5 & 3;
        float* o = out + n * OSTR;
        for (int i = p * 256 + t; i < LV + LA; i += 1024) o[i] = 0.f;
        for (int i = p * 256 + t; i < LV; i += 1024) o[3616 + i] = n_attn_av[n * LV + i];
        for (int i = p * 256 + t; i < LA; i += 1024) o[5184 + i] = n_attn_va[n * LA + i];
    }
}

// KP: per-token prob. grid ((CH_V+CH_A), NN) = 648 blocks, 384 threads = 12 warps (one per head).
// CHUNK=8 tokens per block; all K-row loads + single-sector partial loads issued up front,
// then 8 independent shfl-reduce chains.
__global__ void kp_prob(const float* __restrict__ pos_v_k,
                        const float* __restrict__ pos_a_k,
                        const float* __restrict__ spu_a_cls,
                        const float* __restrict__ spu_v_cls,
                        const int* __restrict__ ids_v,
                        const int* __restrict__ ids_a,
                        const float* __restrict__ u_v,
                        const float* __restrict__ u_a,
                        const float* __restrict__ n_attn_av,
                        const float* __restrict__ n_attn_va,
                        float* __restrict__ out) {
    const int chunk = blockIdx.x;
    const int n = blockIdx.y;
    const bool vside = (chunk < CH_V);
    const int base = (vside ? chunk : chunk - CH_V) * CHUNK;

    const int L = vside ? LV : LA;
    const int* ids = vside ? ids_v : ids_a;
    const float* kk = vside ? pos_v_k : pos_a_k;
    const float* cls = vside ? spu_a_cls : spu_v_cls;
    const float* gpos = vside ? g_vpos : g_apos;   // RS_V == RS_A == 8

    const int t = threadIdx.x;
    const int h = t >> 5;
    const int lane = t & 31;
    const int nh = n * HH + h;

    __shared__ int s_rows[CHUNK];
    __shared__ float s_sig[HH * CHUNK];

    if (t < CHUNK) s_rows[t] = ids[n * L + base + t];

    const float2 c2 = __ldg((const float2*)(cls + (size_t)nh * DHD) + lane);
    const float inv = vside ? (1.f / g_sum_va[n]) : (1.f / g_sum_av[n]);
    __syncthreads();

    // Phase 1: issue all loads (independent; high MLP).
    // Partials are interleaved: 8 partials of (nh,row) are contiguous (one sector).
    float2 a2[CHUNK];
    float gp[CHUNK];
    const float2* kbase = (const float2*)(kk + (size_t)nh * L * DHD);
#pragma unroll
    for (int tok = 0; tok < CHUNK; tok++) {
        const int row = s_rows[tok];
        a2[tok] = __ldg(kbase + (size_t)row * (DHD / 2) + lane);
        gp[tok] = (lane < 8) ? __ldg(&gpos[((size_t)nh * L + row) * 8 + lane]) : 0.f;
    }

    // Phase 2: 8 independent reduce chains
#pragma unroll
    for (int tok = 0; tok < CHUNK; tok++) {
        float val = (a2[tok].x * c2.x + a2[tok].y * c2.y) * SCALEF - gp[tok] * inv;
#pragma unroll
        for (int s = 16; s > 0; s >>= 1) val += __shfl_xor_sync(0xffffffff, val, s);
        if (lane == 0)
            s_sig[h * CHUNK + tok] = 1.f / (1.f + __expf(-val));   // sigmoid(spu - vp)
    }
    __syncthreads();

    if (t < CHUNK) {
        float prob = 0.f;
#pragma unroll
        for (int hh = 0; hh < HH; hh++) prob += s_sig[hh * CHUNK + t];
        prob *= (1.f / HH);
        const int row = s_rows[t];
        float* o = out + n * OSTR;
        if (vside) {
            o[row] = prob;
            float uu = u_v[n * LV + row];
            o[3616 + row] = (uu < prob) ? 0.f : n_attn_av[n * LV + row];
        } else {
            o[1568 + row] = prob;
            float uu = u_a[n * LA + row];
            o[5184 + row] = (uu < prob) ? 0.f : n_attn_va[n * LA + row];
        }
    }
}

extern "C" void kernel_launch(void* const* d_in, const int* in_sizes, int n_in,
                              void* d_out, int out_size) {
    const float* pos_v_q   = (const float*)d_in[0];
    const float* pos_v_k   = (const float*)d_in[1];
    const float* pos_a_q   = (const float*)d_in[2];
    const float* pos_a_k   = (const float*)d_in[3];
    const float* cross_av  = (const float*)d_in[4];
    const float* cross_va  = (const float*)d_in[5];
    const float* n_attn_av = (const float*)d_in[6];
    const float* n_attn_va = (const float*)d_in[7];
    const float* spu_a_cls = (const float*)d_in[8];
    const float* spu_v_cls = (const float*)d_in[9];
    const float* u_v       = (const float*)d_in[10];
    const float* u_a       = (const float*)d_in[11];
    const int*   ids_v     = (const int*)d_in[12];
    const int*   ids_a     = (const int*)d_in[13];
    float* out = (float*)d_out;

    kbig<<<K1_BLOCKS + K2_BLOCKS + K3_BLOCKS + SUM_BLOCKS + FILL_BLOCKS, 256>>>(
        cross_av, cross_va, pos_v_q, pos_a_q, ids_a, ids_v,
        n_attn_av, n_attn_va, out);
    kp_prob<<<dim3(CH_V + CH_A, NN), 384>>>(pos_v_k, pos_a_k, spu_a_cls, spu_v_cls,
                                            ids_v, ids_a, u_v, u_a,
                                            n_attn_av, n_attn_va, out);
}